// round 16
// baseline (speedup 1.0000x reference)
#include <cuda_runtime.h>
#include <math.h>

#define HH 256
#define WW_ 256
#define SHIFT 4
#define STR 36     // packed smem row stride (u32 words); 144 B rows
#define WSZ 13824  // u32 words per window region

typedef unsigned long long ull;
#define PK2(d, lo, hi) asm("mov.b64 %0, {%1, %2};" : "=l"(d) : "f"(lo), "f"(hi))
#define UPK2(lo, hi, s) asm("mov.b64 {%0, %1}, %2;" : "=f"(lo), "=f"(hi) : "l"(s))
#define FMA2(d, a, b, c) asm("fma.rn.f32x2 %0, %1, %2, %3;" : "=l"(d) : "l"(a), "l"(b), "l"(c))
#define MUL2(d, a, b) asm("mul.rn.f32x2 %0, %1, %2;" : "=l"(d) : "l"(a), "l"(b))

// Fragment-order pre-split tables (uint4 = one LDG.128 per fragment feed).
__device__ uint4 g_w2f[2048];        // kv_w  A-order (128 rows)
__device__ uint4 g_pwf[1024];        // proj_w A-order (64 rows)
__device__ uint4 g_qpf[8 * 1024];    // qn [b], rows=c, k=p   B-order
__device__ uint4 g_qcf[8 * 1024];    // qn [b], rows=p, k=c   B-order

__device__ __forceinline__ unsigned pack_bf2(float v0, float v1) {
    unsigned d;
    asm("cvt.rn.bf16x2.f32 %0, %1, %2;" : "=r"(d) : "f"(v1), "f"(v0));  // lo16=v0, hi16=v1
    return d;
}
__device__ __forceinline__ uint2 split_pair(float v0, float v1) {
    unsigned h = pack_bf2(v0, v1);
    float h0 = __uint_as_float(h << 16);
    float h1 = __uint_as_float(h & 0xffff0000u);
    return make_uint2(h, pack_bf2(v0 - h0, v1 - h1));
}

// Single prep launch: blocks 0-7 handle q (per-batch), 8-23 kv_w, 24-31 proj_w.
__global__ void prep(const float* __restrict__ q,
                     const float* __restrict__ kv_w,
                     const float* __restrict__ proj_w) {
    const int tid = threadIdx.x;
    if (blockIdx.x < 8) {
        const int b = blockIdx.x;
        __shared__ float qs[4096];
        __shared__ float innorm[64];
        for (int i = tid; i < 4096; i += 256) qs[i] = q[b * 4096 + i];
        __syncthreads();
        int wid = tid >> 5, lane = tid & 31;
        for (int r = wid; r < 64; r += 8) {
            float v0 = qs[r * 64 + lane], v1 = qs[r * 64 + 32 + lane];
            float ss = v0 * v0 + v1 * v1;
#pragma unroll
            for (int o = 16; o; o >>= 1) ss += __shfl_xor_sync(0xffffffffu, ss, o);
            if (lane == 0) innorm[r] = 1.f / fmaxf(sqrtf(ss), 1e-12f);
        }
        __syncthreads();
        for (int rec = tid; rec < 1024; rec += 256) {
            int tq = rec & 3, g = (rec >> 2) & 7, s = (rec >> 5) & 3, nt = rec >> 7;
            int row = nt * 8 + g;
            float inv = innorm[row];
            int e0 = 16 * s + 2 * tq;
            uint2 u0 = split_pair(qs[row * 64 + e0] * inv, qs[row * 64 + e0 + 1] * inv);
            uint2 u1 = split_pair(qs[row * 64 + e0 + 8] * inv, qs[row * 64 + e0 + 9] * inv);
            g_qpf[b * 1024 + rec] = make_uint4(u0.x, u0.y, u1.x, u1.y);
            int c0 = 16 * s + 2 * tq;
            uint2 w0 = split_pair(qs[c0 * 64 + row] * innorm[c0],
                                  qs[(c0 + 1) * 64 + row] * innorm[c0 + 1]);
            uint2 w1 = split_pair(qs[(c0 + 8) * 64 + row] * innorm[c0 + 8],
                                  qs[(c0 + 9) * 64 + row] * innorm[c0 + 9]);
            g_qcf[b * 1024 + rec] = make_uint4(w0.x, w0.y, w1.x, w1.y);
        }
    } else if (blockIdx.x < 24) {
        int rec = (blockIdx.x - 8) * 256 + tid;
        if (rec < 2048) {
            int half = rec & 1, tq = (rec >> 1) & 3, g = (rec >> 3) & 7;
            int s = (rec >> 6) & 3, mb = rec >> 8;
            int r0 = mb * 16 + g, r1 = r0 + 8;
            int e = 2 * (8 * s + tq + 4 * half);
            uint2 u0 = split_pair(kv_w[r0 * 64 + e], kv_w[r0 * 64 + e + 1]);
            uint2 u1 = split_pair(kv_w[r1 * 64 + e], kv_w[r1 * 64 + e + 1]);
            g_w2f[rec] = make_uint4(u0.x, u0.y, u1.x, u1.y);
        }
    } else {
        int rec = (blockIdx.x - 24) * 256 + tid;
        if (rec < 1024) {
            int half = rec & 1, tq = (rec >> 1) & 3, g = (rec >> 3) & 7;
            int s = (rec >> 6) & 3, mb = rec >> 8;
            int r0 = mb * 16 + g, r1 = r0 + 8;
            int e = 2 * (8 * s + tq + 4 * half);
            uint2 u0 = split_pair(proj_w[r0 * 64 + e], proj_w[r0 * 64 + e + 1]);
            uint2 u1 = split_pair(proj_w[r1 * 64 + e], proj_w[r1 * 64 + e + 1]);
            g_pwf[rec] = make_uint4(u0.x, u0.y, u1.x, u1.y);
        }
    }
}

__device__ __forceinline__ void mma16(float (&d)[4], const unsigned (&a)[4], const unsigned (&b)[2]) {
    asm("mma.sync.aligned.m16n8k16.row.col.f32.bf16.bf16.f32 "
        "{%0,%1,%2,%3}, {%4,%5,%6,%7}, {%8,%9}, {%0,%1,%2,%3};"
        : "+f"(d[0]), "+f"(d[1]), "+f"(d[2]), "+f"(d[3])
        : "r"(a[0]), "r"(a[1]), "r"(a[2]), "r"(a[3]), "r"(b[0]), "r"(b[1]));
}
__device__ __forceinline__ void mma3(float (&d)[4], const unsigned (&ah)[4], const unsigned (&al)[4],
                                     const unsigned (&bh)[2], const unsigned (&bl)[2]) {
    mma16(d, al, bh);
    mma16(d, ah, bl);
    mma16(d, ah, bh);
}

__device__ __forceinline__ unsigned sptr(const void* p) {
    return (unsigned)__cvta_generic_to_shared(p);
}
__device__ __forceinline__ void ldsm4(unsigned (&r)[4], unsigned addr) {
    asm volatile("ldmatrix.sync.aligned.m8n8.x4.shared.b16 {%0,%1,%2,%3}, [%4];"
        : "=r"(r[0]), "=r"(r[1]), "=r"(r[2]), "=r"(r[3]) : "r"(addr));
}
__device__ __forceinline__ void ldsm4t(unsigned (&r)[4], unsigned addr) {
    asm volatile("ldmatrix.sync.aligned.m8n8.x4.trans.shared.b16 {%0,%1,%2,%3}, [%4];"
        : "=r"(r[0]), "=r"(r[1]), "=r"(r[2]), "=r"(r[3]) : "r"(addr));
}

// Per-window smem region (u32 words, base = su + u*WSZ):
//  [0,4608)      XC_H/XC_L -> A1_H/A1_L -> OC_H/OC_L
//  [4608,9216)   KN_H/KN_L -> A2_H/A2_L -> PT (f32 out2 partials, 64x72)
//  [9216,13824)  V_H/V_L
// Two windows per CTA: 27648 u32 = 110,592 B -> 2 CTAs/SM.
__global__ __launch_bounds__(256, 2) void win_kernel(
    const float* __restrict__ x,
    const float* __restrict__ dw_w,
    const float* __restrict__ rs1,
    const float* __restrict__ rs2,
    float* __restrict__ out)
{
    extern __shared__ unsigned su[];

    const int tid  = threadIdx.x;
    const int wid  = tid >> 5;
    const int lane = tid & 31;
    const int g = lane >> 2, tq = lane & 3;
    const unsigned FULL = 0xffffffffu;

    const int rr  = lane & 7;
    const int bB  = (lane >> 3) & 1;
    const int bA  = (lane >> 4) & 1;
    const int ntl = (lane >> 4) & 1;
    const int rhA = (lane >> 3) & 1;

    const int bw2 = blockIdx.x;           // 0..4095 (window pairs)
    const int b   = bw2 >> 9;
    const int wl  = (bw2 & 511) * 2;      // first window in pair
    const int wh  = wl >> 5;              // same for both windows
    const int ww0 = wl & 31;              // even; pair = ww0, ww0+1
    const float r1v = rs1[0], r2v = rs2[0];
    const uint4* __restrict__ qpb = g_qpf + b * 1024;
    const uint4* __restrict__ qcb = g_qcf + b * 1024;

    // ---- P0: load both X windows (roll -4), pack pairs along c ----
    const float* xb = x + (size_t)b * 64 * HH * WW_;
    for (int idx = tid; idx < 4096; idx += 256) {
        int u = idx >> 11, rem = idx & 2047;
        int p = rem & 63, cw = rem >> 6;
        int gh = (wh * 8 + (p >> 3) + SHIFT) & 255;
        int gw = ((ww0 + u) * 8 + (p & 7) + SHIFT) & 255;
        size_t off = (size_t)gh * WW_ + gw;
        float v0 = xb[(size_t)(2 * cw) * HH * WW_ + off];
        float v1 = xb[(size_t)(2 * cw + 1) * HH * WW_ + off];
        uint2 pr = split_pair(v0, v1);
        su[u * WSZ + p * STR + cw] = pr.x;
        su[u * WSZ + 2304 + p * STR + cw] = pr.y;
    }
    __syncthreads();

    // ---- P2: conv1x1 both windows (shared A recs) + dwconv + norm + pack ----
    {
        float acc[2][8][4];
#pragma unroll
        for (int u = 0; u < 2; u++)
#pragma unroll
            for (int i = 0; i < 8; i++)
#pragma unroll
                for (int j = 0; j < 4; j++) acc[u][i][j] = 0.f;
        const unsigned x0 = sptr(su);
#pragma unroll
        for (int s = 0; s < 4; s++) {
            int recA = (((wid * 4 + s) * 8 + g) * 4 + tq) * 2;
            uint4 A0 = __ldg(&g_w2f[recA]);
            uint4 A1v = __ldg(&g_w2f[recA + 1]);
            unsigned ah[4] = {A0.x, A0.z, A1v.x, A1v.z};
            unsigned al[4] = {A0.y, A0.w, A1v.y, A1v.w};
#pragma unroll
            for (int np = 0; np < 4; np++) {
                unsigned ro = ((np * 2 + ntl) * 8 + rr) * 144 + bB * 16 + s * 32;
#pragma unroll
                for (int u = 0; u < 2; u++) {
                    unsigned bhr[4], blr[4];
                    ldsm4(bhr, x0 + u * (WSZ * 4) + ro);
                    ldsm4(blr, x0 + u * (WSZ * 4) + 9216 + ro);
                    unsigned bh0[2] = {bhr[0], bhr[1]}, bl0[2] = {blr[0], blr[1]};
                    unsigned bh1[2] = {bhr[2], bhr[3]}, bl1[2] = {blr[2], blr[3]};
                    mma3(acc[u][np * 2],     ah, al, bh0, bl0);
                    mma3(acc[u][np * 2 + 1], ah, al, bh1, bl1);
                }
            }
        }
        __syncthreads();   // all X reads done (A1 pack may later reuse region)
#pragma unroll
        for (int h = 0; h < 2; h++) {
            const int oc = wid * 16 + 8 * h + g;
            ull wp[9];
#pragma unroll
            for (int q9 = 0; q9 < 9; q9++) {
                float wv = __ldg(&dw_w[oc * 9 + q9]);
                PK2(wp[q9], wv, wv);
            }
#pragma unroll
            for (int u = 0; u < 2; u++) {
                ull o[8];
#pragma unroll
                for (int i = 0; i < 8; i++) o[i] = 0ULL;
#pragma unroll
                for (int ii = 0; ii < 8; ii++) {
                    float c0 = acc[u][ii][2 * h], c1 = acc[u][ii][2 * h + 1];
                    float Lv = __shfl_up_sync(FULL, c1, 1);
                    float Rv = __shfl_down_sync(FULL, c0, 1);
                    if (tq == 0) Lv = 0.f;
                    if (tq == 3) Rv = 0.f;
                    ull p0, p1, p2;
                    PK2(p0, Lv, c0);
                    PK2(p1, c0, c1);
                    PK2(p2, c1, Rv);
#pragma unroll
                    for (int dy = 0; dy < 3; dy++) {
                        int i = ii + 1 - dy;
                        if (i < 0 || i > 7) continue;
                        FMA2(o[i], wp[dy * 3 + 0], p0, o[i]);
                        FMA2(o[i], wp[dy * 3 + 1], p1, o[i]);
                        FMA2(o[i], wp[dy * 3 + 2], p2, o[i]);
                    }
                }
                unsigned* base = su + u * WSZ;
                unsigned* DH; unsigned* DL; int row;
                if (wid < 4) {   // K rows: l2-normalize
                    ull ss2 = 0ULL;
#pragma unroll
                    for (int i = 0; i < 8; i++) FMA2(ss2, o[i], o[i], ss2);
                    float sa, sb;
                    UPK2(sa, sb, ss2);
                    float ss = sa + sb;
                    ss += __shfl_xor_sync(FULL, ss, 1);
                    ss += __shfl_xor_sync(FULL, ss, 2);
                    float inv = 1.f / fmaxf(sqrtf(ss), 1e-12f);
                    ull ip;
                    PK2(ip, inv, inv);
#pragma unroll
                    for (int i = 0; i < 8; i++) MUL2(o[i], o[i], ip);
                    DH = base + 4608; DL = base + 6912; row = oc;
                } else {
                    DH = base + 9216; DL = base + 11520; row = oc - 64;
                }
#pragma unroll
                for (int i = 0; i < 8; i++) {
                    float v0, v1;
                    UPK2(v0, v1, o[i]);
                    uint2 pr = split_pair(v0, v1);
                    DH[row * STR + 4 * i + tq] = pr.x;
                    DL[row * STR + 4 * i + tq] = pr.y;
                }
            }
        }
    }
    __syncthreads();

    // ---- P3: S-GEMM both windows + max-free softmax -> pack A1/A2 to smem ----
    const int mat = wid >> 2;
    const int m0 = (wid & 3) * 16;
    {
        const float rv = mat ? r2v : r1v;
        float acc[2][8][4];
#pragma unroll
        for (int u = 0; u < 2; u++)
#pragma unroll
            for (int i = 0; i < 8; i++)
#pragma unroll
                for (int j = 0; j < 4; j++) acc[u][i][j] = 0.f;
        const unsigned s0 = sptr(su);
        const unsigned aoffb = (m0 + rhA * 8 + rr) * 144 + bA * 16;
#pragma unroll
        for (int s = 0; s < 4; s++) {
            unsigned ah[2][4], al[2][4];
#pragma unroll
            for (int u = 0; u < 2; u++) {
                ldsm4(ah[u], s0 + u * (WSZ * 4) + 18432 + aoffb + s * 32);  // KNH
                ldsm4(al[u], s0 + u * (WSZ * 4) + 27648 + aoffb + s * 32);  // KNL
            }
            if (mat == 0) {
#pragma unroll
                for (int nt = 0; nt < 8; nt++) {
                    uint4 Q = __ldg(&qpb[((nt * 4 + s) * 8 + g) * 4 + tq]);
                    unsigned bh[2] = {Q.x, Q.z}, bl[2] = {Q.y, Q.w};
                    mma3(acc[0][nt], ah[0], al[0], bh, bl);
                    mma3(acc[1][nt], ah[1], al[1], bh, bl);
                }
            } else {
#pragma unroll
                for (int np = 0; np < 4; np++) {
                    unsigned ro = ((np * 2 + ntl) * 8 + rr) * 144 + bB * 16 + s * 32;
#pragma unroll
                    for (int u = 0; u < 2; u++) {
                        unsigned bhr[4], blr[4];
                        ldsm4(bhr, s0 + u * (WSZ * 4) + 36864 + ro);  // VH
                        ldsm4(blr, s0 + u * (WSZ * 4) + 46080 + ro);  // VL
                        unsigned bh0[2] = {bhr[0], bhr[1]}, bl0[2] = {blr[0], blr[1]};
                        unsigned bh1[2] = {bhr[2], bhr[3]}, bl1[2] = {blr[2], blr[3]};
                        mma3(acc[u][np * 2],     ah[u], al[u], bh0, bl0);
                        mma3(acc[u][np * 2 + 1], ah[u], al[u], bh1, bl1);
                    }
                }
            }
        }
        // Max-free softmax (|S1|<=rv cosine sims, |S2| small)
#pragma unroll
        for (int u = 0; u < 2; u++)
#pragma unroll
            for (int h = 0; h < 2; h++) {
                float ssum = 0.f;
#pragma unroll
                for (int nt = 0; nt < 8; nt++) {
                    acc[u][nt][2 * h]     = __expf(acc[u][nt][2 * h] * rv);
                    acc[u][nt][2 * h + 1] = __expf(acc[u][nt][2 * h + 1] * rv);
                    ssum += acc[u][nt][2 * h] + acc[u][nt][2 * h + 1];
                }
                ssum += __shfl_xor_sync(FULL, ssum, 1);
                ssum += __shfl_xor_sync(FULL, ssum, 2);
                float inv = 1.f / ssum;
#pragma unroll
                for (int nt = 0; nt < 8; nt++) {
                    acc[u][nt][2 * h] *= inv; acc[u][nt][2 * h + 1] *= inv;
                }
            }
        __syncthreads();   // all KN reads done (A2 overlays KN)
#pragma unroll
        for (int u = 0; u < 2; u++) {
            unsigned* base = su + u * WSZ;
            unsigned* DH = mat ? (base + 4608) : base;          // A2 : A1
            unsigned* DL = mat ? (base + 6912) : (base + 2304);
#pragma unroll
            for (int h = 0; h < 2; h++) {
                int row = m0 + g + 8 * h;
#pragma unroll
                for (int nt = 0; nt < 8; nt++) {
                    uint2 pr = split_pair(acc[u][nt][2 * h], acc[u][nt][2 * h + 1]);
                    DH[row * STR + 4 * nt + tq] = pr.x;
                    DL[row * STR + 4 * nt + tq] = pr.y;
                }
            }
        }
    }
    __syncthreads();

    // ---- P4: out-GEMMs. mat1 -> PT (over A2, named-barrier); mat0 merges -> OC ----
    {
        const unsigned s0 = sptr(su);
        const unsigned aoffb = (m0 + rhA * 8 + rr) * 144 + bA * 16;
        float acc[2][8][4];
#pragma unroll
        for (int u = 0; u < 2; u++)
#pragma unroll
            for (int i = 0; i < 8; i++)
#pragma unroll
                for (int j = 0; j < 4; j++) acc[u][i][j] = 0.f;

        if (mat == 0) {
            // out1 = A1 @ V, full n=64, both windows
#pragma unroll
            for (int s = 0; s < 4; s++) {
                unsigned a1h[2][4], a1l[2][4];
#pragma unroll
                for (int u = 0; u < 2; u++) {
                    ldsm4(a1h[u], s0 + u * (WSZ * 4) + aoffb + s * 32);         // A1H
                    ldsm4(a1l[u], s0 + u * (WSZ * 4) + 9216 + aoffb + s * 32);  // A1L
                }
#pragma unroll
                for (int np = 0; np < 4; np++) {
                    unsigned vo = (16 * s + bB * 8 + rr) * 144 + ((np * 2 + ntl) * 8) * 2;
#pragma unroll
                    for (int u = 0; u < 2; u++) {
                        unsigned bhr[4], blr[4];
                        ldsm4t(bhr, s0 + u * (WSZ * 4) + 36864 + vo);  // VH
                        ldsm4t(blr, s0 + u * (WSZ * 4) + 46080 + vo);  // VL
                        unsigned bh0[2] = {bhr[0], bhr[1]}, bl0[2] = {blr[0], blr[1]};
                        unsigned bh1[2] = {bhr[2], bhr[3]}, bl1[2] = {blr[2], blr[3]};
                        mma3(acc[u][np * 2],     a1h[u], a1l[u], bh0, bl0);
                        mma3(acc[u][np * 2 + 1], a1h[u], a1l[u], bh1, bl1);
                    }
                }
            }
        } else {
            // out2 = A2 @ qn (qc records shared across windows)
#pragma unroll
            for (int s = 0; s < 4; s++) {
                unsigned a2h[2][4], a2l[2][4];
#pragma unroll
                for (int u = 0; u < 2; u++) {
                    ldsm4(a2h[u], s0 + u * (WSZ * 4) + 18432 + aoffb + s * 32);  // A2H
                    ldsm4(a2l[u], s0 + u * (WSZ * 4) + 27648 + aoffb + s * 32);  // A2L
                }
#pragma unroll
                for (int nt = 0; nt < 8; nt++) {
                    uint4 Q = __ldg(&qcb[((nt * 4 + s) * 8 + g) * 4 + tq]);
                    unsigned bh[2] = {Q.x, Q.z}, bl[2] = {Q.y, Q.w};
                    mma3(acc[0][nt], a2h[0], a2l[0], bh, bl);
                    mma3(acc[1][nt], a2h[1], a2l[1], bh, bl);
                }
            }
            asm volatile("bar.sync 1, 128;" ::: "memory");  // mat1 A2 reads done
#pragma unroll
            for (int u = 0; u < 2; u++) {
                float* PT = (float*)(su + u * WSZ + 4608);
#pragma unroll
                for (int nt = 0; nt < 8; nt++) {
                    int c = 8 * nt + 2 * tq;
                    *(float2*)&PT[(m0 + g) * 72 + c]     = make_float2(acc[u][nt][0], acc[u][nt][1]);
                    *(float2*)&PT[(m0 + g + 8) * 72 + c] = make_float2(acc[u][nt][2], acc[u][nt][3]);
                }
            }
        }
        __syncthreads();   // PT ready; all A1 reads done

        if (mat == 0) {
            const bool evn = ((g & 1) == 0);
#pragma unroll
            for (int u = 0; u < 2; u++) {
                const float* PT = (const float*)(su + u * WSZ + 4608);
                unsigned* OCH = su + u * WSZ;
                unsigned* OCL = su + u * WSZ + 2304;
#pragma unroll
                for (int nt = 0; nt < 8; nt++) {
                    int c = 8 * nt + 2 * tq;
                    float2 p0 = *(const float2*)&PT[(m0 + g) * 72 + c];
                    float2 p1 = *(const float2*)&PT[(m0 + g + 8) * 72 + c];
                    acc[u][nt][0] += p0.x; acc[u][nt][1] += p0.y;
                    acc[u][nt][2] += p1.x; acc[u][nt][3] += p1.y;
                    float pv0 = __shfl_xor_sync(FULL, acc[u][nt][0], 4);
                    float pv1 = __shfl_xor_sync(FULL, acc[u][nt][1], 4);
                    float pv2 = __shfl_xor_sync(FULL, acc[u][nt][2], 4);
                    float pv3 = __shfl_xor_sync(FULL, acc[u][nt][3], 4);
                    uint2 w0, w1;
                    int cw;
                    if (evn) {
                        w0 = split_pair(acc[u][nt][0], pv0);
                        w1 = split_pair(acc[u][nt][1], pv1);
                        cw = (m0 + g) >> 1;
                    } else {
                        w0 = split_pair(pv2, acc[u][nt][2]);
                        w1 = split_pair(pv3, acc[u][nt][3]);
                        cw = (m0 + g + 7) >> 1;
                    }
                    OCH[c * STR + cw] = w0.x;
                    OCL[c * STR + cw] = w0.y;
                    OCH[(c + 1) * STR + cw] = w1.x;
                    OCL[(c + 1) * STR + cw] = w1.y;
                }
            }
        }
    }
    __syncthreads();

    // ---- P6: proj both windows (shared pwf A recs) -> gmem (roll +4) ----
    {
        const int n0 = (wid >> 2) * 32;
        const unsigned s0 = sptr(su);
        float acc[2][4][4];
#pragma unroll
        for (int u = 0; u < 2; u++)
#pragma unroll
            for (int i = 0; i < 4; i++)
#pragma unroll
                for (int j = 0; j < 4; j++) acc[u][i][j] = 0.f;
#pragma unroll
        for (int s = 0; s < 4; s++) {
            int recA = ((((wid & 3) * 4 + s) * 8 + g) * 4 + tq) * 2;
            uint4 A0 = __ldg(&g_pwf[recA]);
            uint4 A1v = __ldg(&g_pwf[recA + 1]);
            unsigned ah[4] = {A0.x, A0.z, A1v.x, A1v.z};
            unsigned al[4] = {A0.y, A0.w, A1v.y, A1v.w};
#pragma unroll
            for (int np = 0; np < 2; np++) {
                unsigned ro = (n0 + (np * 2 + ntl) * 8 + rr) * 144 + bB * 16 + s * 32;
#pragma unroll
                for (int u = 0; u < 2; u++) {
                    unsigned bhr[4], blr[4];
                    ldsm4(bhr, s0 + u * (WSZ * 4) + ro);         // OCH
                    ldsm4(blr, s0 + u * (WSZ * 4) + 9216 + ro);  // OCL
                    unsigned bh0[2] = {bhr[0], bhr[1]}, bl0[2] = {blr[0], blr[1]};
                    unsigned bh1[2] = {bhr[2], bhr[3]}, bl1[2] = {blr[2], blr[3]};
                    mma3(acc[u][np * 2],     ah, al, bh0, bl0);
                    mma3(acc[u][np * 2 + 1], ah, al, bh1, bl1);
                }
            }
        }
        float* ob = out + (size_t)b * 64 * HH * WW_;
#pragma unroll
        for (int u = 0; u < 2; u++) {
#pragma unroll
            for (int nt = 0; nt < 4; nt++) {
                int c = n0 + 8 * nt + 2 * tq;
                int pi = c >> 3;
                int gh = (wh * 8 + pi + SHIFT) & 255;
                int gw = ((ww0 + u) * 8 + (c & 7) + SHIFT) & 255;
#pragma unroll
                for (int ri = 0; ri < 2; ri++) {
                    int r = m0 + g + ri * 8;
                    *(float2*)&ob[(size_t)r * HH * WW_ + (size_t)gh * WW_ + gw] =
                        make_float2(acc[u][nt][ri * 2], acc[u][nt][ri * 2 + 1]);
                }
            }
        }
    }
}

extern "C" void kernel_launch(void* const* d_in, const int* in_sizes, int n_in,
                              void* d_out, int out_size) {
    const float* x      = (const float*)d_in[0];
    const float* q      = (const float*)d_in[1];
    const float* kv_w   = (const float*)d_in[2];
    const float* dw_w   = (const float*)d_in[3];
    const float* proj_w = (const float*)d_in[4];
    const float* rs1    = (const float*)d_in[5];
    const float* rs2    = (const float*)d_in[6];
    float* out = (float*)d_out;

    static bool attr_set = false;
    const int smem_bytes = 2 * WSZ * 4;  // 110,592 B
    if (!attr_set) {
        cudaFuncSetAttribute(win_kernel,
                             cudaFuncAttributeMaxDynamicSharedMemorySize,
                             smem_bytes);
        attr_set = true;
    }

    prep<<<32, 256>>>(q, kv_w, proj_w);
    win_kernel<<<4096, 256, smem_bytes>>>(x, dw_w, rs1, rs2, out);
}

// round 17
// speedup vs baseline: 1.1471x; 1.1471x over previous
#include <cuda_runtime.h>
#include <math.h>

#define HH 256
#define WW_ 256
#define SHIFT 4
#define STR 36   // packed smem row stride (u32 words); 144 B rows

typedef unsigned long long ull;
#define PK2(d, lo, hi) asm("mov.b64 %0, {%1, %2};" : "=l"(d) : "f"(lo), "f"(hi))
#define UPK2(lo, hi, s) asm("mov.b64 {%0, %1}, %2;" : "=f"(lo), "=f"(hi) : "l"(s))
#define FMA2(d, a, b, c) asm("fma.rn.f32x2 %0, %1, %2, %3;" : "=l"(d) : "l"(a), "l"(b), "l"(c))
#define MUL2(d, a, b) asm("mul.rn.f32x2 %0, %1, %2;" : "=l"(d) : "l"(a), "l"(b))

// Fragment-order pre-split tables (uint4 = one LDG.128 per fragment feed).
__device__ uint4 g_w2f[2048];        // kv_w  A-order (128 rows)
__device__ uint4 g_pwf[1024];        // proj_w A-order (64 rows)
__device__ uint4 g_qpf[8 * 1024];    // qn [b], rows=c, k=p   B-order
__device__ uint4 g_qcf[8 * 1024];    // qn [b], rows=p, k=c   B-order

__device__ __forceinline__ unsigned pack_bf2(float v0, float v1) {
    unsigned d;
    asm("cvt.rn.bf16x2.f32 %0, %1, %2;" : "=r"(d) : "f"(v1), "f"(v0));  // lo16=v0, hi16=v1
    return d;
}
__device__ __forceinline__ uint2 split_pair(float v0, float v1) {
    unsigned h = pack_bf2(v0, v1);
    float h0 = __uint_as_float(h << 16);
    float h1 = __uint_as_float(h & 0xffff0000u);
    return make_uint2(h, pack_bf2(v0 - h0, v1 - h1));
}

// Single prep launch: blocks 0-7 handle q (per-batch), 8-23 kv_w, 24-31 proj_w.
__global__ void prep(const float* __restrict__ q,
                     const float* __restrict__ kv_w,
                     const float* __restrict__ proj_w) {
    const int tid = threadIdx.x;
    if (blockIdx.x < 8) {
        const int b = blockIdx.x;
        __shared__ float qs[4096];
        __shared__ float innorm[64];
        // float4 staging: 1024 vec loads over 256 threads = 4 each
        {
            const float4* q4 = (const float4*)(q + b * 4096);
            float4* s4 = (float4*)qs;
#pragma unroll
            for (int k = 0; k < 4; k++) s4[tid + 256 * k] = q4[tid + 256 * k];
        }
        __syncthreads();
        int wid = tid >> 5, lane = tid & 31;
        for (int r = wid; r < 64; r += 8) {
            float v0 = qs[r * 64 + lane], v1 = qs[r * 64 + 32 + lane];
            float ss = v0 * v0 + v1 * v1;
#pragma unroll
            for (int o = 16; o; o >>= 1) ss += __shfl_xor_sync(0xffffffffu, ss, o);
            if (lane == 0) innorm[r] = 1.f / fmaxf(sqrtf(ss), 1e-12f);
        }
        __syncthreads();
        for (int rec = tid; rec < 1024; rec += 256) {
            int tq = rec & 3, g = (rec >> 2) & 7, s = (rec >> 5) & 3, nt = rec >> 7;
            int row = nt * 8 + g;
            float inv = innorm[row];
            int e0 = 16 * s + 2 * tq;
            uint2 u0 = split_pair(qs[row * 64 + e0] * inv, qs[row * 64 + e0 + 1] * inv);
            uint2 u1 = split_pair(qs[row * 64 + e0 + 8] * inv, qs[row * 64 + e0 + 9] * inv);
            g_qpf[b * 1024 + rec] = make_uint4(u0.x, u0.y, u1.x, u1.y);
            int c0 = 16 * s + 2 * tq;
            uint2 w0 = split_pair(qs[c0 * 64 + row] * innorm[c0],
                                  qs[(c0 + 1) * 64 + row] * innorm[c0 + 1]);
            uint2 w1 = split_pair(qs[(c0 + 8) * 64 + row] * innorm[c0 + 8],
                                  qs[(c0 + 9) * 64 + row] * innorm[c0 + 9]);
            g_qcf[b * 1024 + rec] = make_uint4(w0.x, w0.y, w1.x, w1.y);
        }
    } else if (blockIdx.x < 24) {
        int rec = (blockIdx.x - 8) * 256 + tid;
        if (rec < 2048) {
            int half = rec & 1, tq = (rec >> 1) & 3, g = (rec >> 3) & 7;
            int s = (rec >> 6) & 3, mb = rec >> 8;
            int r0 = mb * 16 + g, r1 = r0 + 8;
            int e = 2 * (8 * s + tq + 4 * half);
            uint2 u0 = split_pair(kv_w[r0 * 64 + e], kv_w[r0 * 64 + e + 1]);
            uint2 u1 = split_pair(kv_w[r1 * 64 + e], kv_w[r1 * 64 + e + 1]);
            g_w2f[rec] = make_uint4(u0.x, u0.y, u1.x, u1.y);
        }
    } else {
        int rec = (blockIdx.x - 24) * 256 + tid;
        if (rec < 1024) {
            int half = rec & 1, tq = (rec >> 1) & 3, g = (rec >> 3) & 7;
            int s = (rec >> 6) & 3, mb = rec >> 8;
            int r0 = mb * 16 + g, r1 = r0 + 8;
            int e = 2 * (8 * s + tq + 4 * half);
            uint2 u0 = split_pair(proj_w[r0 * 64 + e], proj_w[r0 * 64 + e + 1]);
            uint2 u1 = split_pair(proj_w[r1 * 64 + e], proj_w[r1 * 64 + e + 1]);
            g_pwf[rec] = make_uint4(u0.x, u0.y, u1.x, u1.y);
        }
    }
}

__device__ __forceinline__ void mma16(float (&d)[4], const unsigned (&a)[4], const unsigned (&b)[2]) {
    asm("mma.sync.aligned.m16n8k16.row.col.f32.bf16.bf16.f32 "
        "{%0,%1,%2,%3}, {%4,%5,%6,%7}, {%8,%9}, {%0,%1,%2,%3};"
        : "+f"(d[0]), "+f"(d[1]), "+f"(d[2]), "+f"(d[3])
        : "r"(a[0]), "r"(a[1]), "r"(a[2]), "r"(a[3]), "r"(b[0]), "r"(b[1]));
}
__device__ __forceinline__ void mma3(float (&d)[4], const unsigned (&ah)[4], const unsigned (&al)[4],
                                     const unsigned (&bh)[2], const unsigned (&bl)[2]) {
    mma16(d, al, bh);
    mma16(d, ah, bl);
    mma16(d, ah, bh);
}

__device__ __forceinline__ unsigned sptr(const void* p) {
    return (unsigned)__cvta_generic_to_shared(p);
}
__device__ __forceinline__ void ldsm4(unsigned (&r)[4], unsigned addr) {
    asm volatile("ldmatrix.sync.aligned.m8n8.x4.shared.b16 {%0,%1,%2,%3}, [%4];"
        : "=r"(r[0]), "=r"(r[1]), "=r"(r[2]), "=r"(r[3]) : "r"(addr));
}
__device__ __forceinline__ void ldsm4t(unsigned (&r)[4], unsigned addr) {
    asm volatile("ldmatrix.sync.aligned.m8n8.x4.trans.shared.b16 {%0,%1,%2,%3}, [%4];"
        : "=r"(r[0]), "=r"(r[1]), "=r"(r[2]), "=r"(r[3]) : "r"(addr));
}

// smem u32 layout (total 13824 u32 = 55,296 B; 4 CTAs/SM = 221 KB):
//  [0,4608)      XC_H/XC_L  -> PT (f32 partials, stride 72) in P4
//  [4608,9216)   KN_H/KN_L  -> OC_H/OC_L (packed O)
//  [9216,13824)  V_H/V_L
__global__ __launch_bounds__(256, 4) void win_kernel(
    const float* __restrict__ x,
    const float* __restrict__ dw_w,
    const float* __restrict__ rs1,
    const float* __restrict__ rs2,
    float* __restrict__ out)
{
    extern __shared__ unsigned su[];
    unsigned* XH = su;
    unsigned* XL = su + 2304;
    float*    PT = (float*)su;     // f32 partials, 64 x 72 (after P2; XC dead)
    unsigned* KNH = su + 4608;
    unsigned* KNL = su + 6912;
    unsigned* OCH = su + 4608;     // after P4 (KN dead)
    unsigned* OCL = su + 6912;
    unsigned* VH  = su + 9216;
    unsigned* VL  = su + 11520;

    const int tid  = threadIdx.x;
    const int wid  = tid >> 5;
    const int lane = tid & 31;
    const int g = lane >> 2, tq = lane & 3;
    const unsigned FULL = 0xffffffffu;

    const int rr  = lane & 7;
    const int bB  = (lane >> 3) & 1;
    const int bA  = (lane >> 4) & 1;
    const int ntl = (lane >> 4) & 1;
    const int rhA = (lane >> 3) & 1;

    const int bw = blockIdx.x;
    const int b  = bw >> 10;
    const int w  = bw & 1023;
    const int wh = w >> 5, ww = w & 31;
    const float r1v = rs1[0], r2v = rs2[0];
    const uint4* __restrict__ qpb = g_qpf + b * 1024;
    const uint4* __restrict__ qcb = g_qcf + b * 1024;

    // ---- P0: load X window (roll -4), pack pairs along c ----
    const float* xb = x + (size_t)b * 64 * HH * WW_;
    for (int idx = tid; idx < 2048; idx += 256) {
        int p = idx & 63, cw = idx >> 6;
        int gh = (wh * 8 + (p >> 3) + SHIFT) & 255;
        int gw = (ww * 8 + (p & 7) + SHIFT) & 255;
        size_t off = (size_t)gh * WW_ + gw;
        float v0 = xb[(size_t)(2 * cw) * HH * WW_ + off];
        float v1 = xb[(size_t)(2 * cw + 1) * HH * WW_ + off];
        uint2 pr = split_pair(v0, v1);
        XH[p * STR + cw] = pr.x;
        XL[p * STR + cw] = pr.y;
    }
    __syncthreads();

    // ---- P2: conv1x1 (regs) + in-register dwconv (f32x2) + norm + pack ----
    {
        float acc[8][4];
#pragma unroll
        for (int i = 0; i < 8; i++)
#pragma unroll
            for (int j = 0; j < 4; j++) acc[i][j] = 0.f;
        const unsigned xh0 = sptr(XH), xl0 = sptr(XL);
#pragma unroll
        for (int s = 0; s < 4; s++) {
            int recA = (((wid * 4 + s) * 8 + g) * 4 + tq) * 2;
            uint4 A0 = __ldg(&g_w2f[recA]);
            uint4 A1v = __ldg(&g_w2f[recA + 1]);
            unsigned ah[4] = {A0.x, A0.z, A1v.x, A1v.z};
            unsigned al[4] = {A0.y, A0.w, A1v.y, A1v.w};
#pragma unroll
            for (int np = 0; np < 4; np++) {
                unsigned ro = ((np * 2 + ntl) * 8 + rr) * 144 + bB * 16 + s * 32;
                unsigned bhr[4], blr[4];
                ldsm4(bhr, xh0 + ro);
                ldsm4(blr, xl0 + ro);
                unsigned bh0[2] = {bhr[0], bhr[1]}, bl0[2] = {blr[0], blr[1]};
                unsigned bh1[2] = {bhr[2], bhr[3]}, bl1[2] = {blr[2], blr[3]};
                mma3(acc[np * 2],     ah, al, bh0, bl0);
                mma3(acc[np * 2 + 1], ah, al, bh1, bl1);
            }
        }
#pragma unroll
        for (int h = 0; h < 2; h++) {
            const int oc = wid * 16 + 8 * h + g;
            ull wp[9];
#pragma unroll
            for (int q9 = 0; q9 < 9; q9++) {
                float wv = __ldg(&dw_w[oc * 9 + q9]);
                PK2(wp[q9], wv, wv);
            }
            ull o[8];
#pragma unroll
            for (int i = 0; i < 8; i++) o[i] = 0ULL;
#pragma unroll
            for (int ii = 0; ii < 8; ii++) {
                float c0 = acc[ii][2 * h], c1 = acc[ii][2 * h + 1];
                float Lv = __shfl_up_sync(FULL, c1, 1);
                float Rv = __shfl_down_sync(FULL, c0, 1);
                if (tq == 0) Lv = 0.f;
                if (tq == 3) Rv = 0.f;
                ull p0, p1, p2;
                PK2(p0, Lv, c0);
                PK2(p1, c0, c1);
                PK2(p2, c1, Rv);
#pragma unroll
                for (int dy = 0; dy < 3; dy++) {
                    int i = ii + 1 - dy;
                    if (i < 0 || i > 7) continue;
                    FMA2(o[i], wp[dy * 3 + 0], p0, o[i]);
                    FMA2(o[i], wp[dy * 3 + 1], p1, o[i]);
                    FMA2(o[i], wp[dy * 3 + 2], p2, o[i]);
                }
            }
            unsigned* DH; unsigned* DL; int row;
            if (wid < 4) {   // K: l2-normalize rows (packed square-sum)
                ull ss2 = 0ULL;
#pragma unroll
                for (int i = 0; i < 8; i++) FMA2(ss2, o[i], o[i], ss2);
                float sa, sb;
                UPK2(sa, sb, ss2);
                float ss = sa + sb;
                ss += __shfl_xor_sync(FULL, ss, 1);
                ss += __shfl_xor_sync(FULL, ss, 2);
                float inv = 1.f / fmaxf(sqrtf(ss), 1e-12f);
                ull ip;
                PK2(ip, inv, inv);
#pragma unroll
                for (int i = 0; i < 8; i++) MUL2(o[i], o[i], ip);
                DH = KNH; DL = KNL; row = oc;
            } else {
                DH = VH; DL = VL; row = oc - 64;
            }
#pragma unroll
            for (int i = 0; i < 8; i++) {
                float v0, v1;
                UPK2(v0, v1, o[i]);
                uint2 pr = split_pair(v0, v1);
                DH[row * STR + 4 * i + tq] = pr.x;
                DL[row * STR + 4 * i + tq] = pr.y;
            }
        }
    }
    __syncthreads();

    // ---- P3+P4a: S-GEMM, max-free softmax, register A-frags, out-GEMM ----
    const int mat = wid >> 2;
    const int m0 = (wid & 3) * 16;
    {
        const float rv = mat ? r2v : r1v;
        float acc[8][4];
#pragma unroll
        for (int i = 0; i < 8; i++)
#pragma unroll
            for (int j = 0; j < 4; j++) acc[i][j] = 0.f;
        const unsigned knh0 = sptr(KNH), knl0 = sptr(KNL);
        const unsigned vh0 = sptr(VH), vl0 = sptr(VL);
        const unsigned aoffb = (m0 + rhA * 8 + rr) * 144 + bA * 16;
#pragma unroll
        for (int s = 0; s < 4; s++) {
            unsigned ah[4], al[4];
            ldsm4(ah, knh0 + aoffb + s * 32);
            ldsm4(al, knl0 + aoffb + s * 32);
            if (mat == 0) {
#pragma unroll
                for (int nt = 0; nt < 8; nt++) {
                    uint4 Q = __ldg(&qpb[((nt * 4 + s) * 8 + g) * 4 + tq]);
                    unsigned bh[2] = {Q.x, Q.z}, bl[2] = {Q.y, Q.w};
                    mma3(acc[nt], ah, al, bh, bl);
                }
            } else {
#pragma unroll
                for (int np = 0; np < 4; np++) {
                    unsigned ro = ((np * 2 + ntl) * 8 + rr) * 144 + bB * 16 + s * 32;
                    unsigned bhr[4], blr[4];
                    ldsm4(bhr, vh0 + ro);
                    ldsm4(blr, vl0 + ro);
                    unsigned bh0[2] = {bhr[0], bhr[1]}, bl0[2] = {blr[0], blr[1]};
                    unsigned bh1[2] = {bhr[2], bhr[3]}, bl1[2] = {blr[2], blr[3]};
                    mma3(acc[np * 2],     ah, al, bh0, bl0);
                    mma3(acc[np * 2 + 1], ah, al, bh1, bl1);
                }
            }
        }
        // Max-free softmax: |S1| <= rv (cosine sims), |S2| small -> exp safe.
#pragma unroll
        for (int h = 0; h < 2; h++) {
            float ssum = 0.f;
#pragma unroll
            for (int nt = 0; nt < 8; nt++) {
                acc[nt][2 * h]     = __expf(acc[nt][2 * h] * rv);
                acc[nt][2 * h + 1] = __expf(acc[nt][2 * h + 1] * rv);
                ssum += acc[nt][2 * h] + acc[nt][2 * h + 1];
            }
            ssum += __shfl_xor_sync(FULL, ssum, 1);
            ssum += __shfl_xor_sync(FULL, ssum, 2);
            float inv = 1.f / ssum;
#pragma unroll
            for (int nt = 0; nt < 8; nt++) {
                acc[nt][2 * h] *= inv; acc[nt][2 * h + 1] *= inv;
            }
        }
        // Build register A-fragments (D-frag layout == A-frag layout)
        unsigned fh[4][4], fl[4][4];
#pragma unroll
        for (int s = 0; s < 4; s++) {
            uint2 sp;
            sp = split_pair(acc[2 * s][0],     acc[2 * s][1]);     fh[s][0] = sp.x; fl[s][0] = sp.y;
            sp = split_pair(acc[2 * s][2],     acc[2 * s][3]);     fh[s][1] = sp.x; fl[s][1] = sp.y;
            sp = split_pair(acc[2 * s + 1][0], acc[2 * s + 1][1]); fh[s][2] = sp.x; fl[s][2] = sp.y;
            sp = split_pair(acc[2 * s + 1][2], acc[2 * s + 1][3]); fh[s][3] = sp.x; fl[s][3] = sp.y;
        }
        // P4a: own-matrix GEMM over full n=64 (reuse acc as output accumulator)
#pragma unroll
        for (int i = 0; i < 8; i++)
#pragma unroll
            for (int j = 0; j < 4; j++) acc[i][j] = 0.f;
        if (mat == 0) {
            // out1 = A1 @ V, B via ldmatrix.trans of V
#pragma unroll
            for (int s = 0; s < 4; s++) {
#pragma unroll
                for (int np = 0; np < 4; np++) {
                    unsigned vo = (16 * s + bB * 8 + rr) * 144 + ((np * 2 + ntl) * 8) * 2;
                    unsigned bhr[4], blr[4];
                    ldsm4t(bhr, vh0 + vo);
                    ldsm4t(blr, vl0 + vo);
                    unsigned bh0[2] = {bhr[0], bhr[1]}, bl0[2] = {blr[0], blr[1]};
                    unsigned bh1[2] = {bhr[2], bhr[3]}, bl1[2] = {blr[2], blr[3]};
                    mma3(acc[np * 2],     fh[s], fl[s], bh0, bl0);
                    mma3(acc[np * 2 + 1], fh[s], fl[s], bh1, bl1);
                }
            }
        } else {
            // out2 = A2 @ qn, B from gmem fragment records
#pragma unroll
            for (int s = 0; s < 4; s++) {
#pragma unroll
                for (int nt = 0; nt < 8; nt++) {
                    uint4 Q = __ldg(&qcb[((nt * 4 + s) * 8 + g) * 4 + tq]);
                    unsigned bh[2] = {Q.x, Q.z}, bl[2] = {Q.y, Q.w};
                    mma3(acc[nt], fh[s], fl[s], bh, bl);
                }
            }
            // store f32 partials (stride 72: conflict-free STS.64)
#pragma unroll
            for (int nt = 0; nt < 8; nt++) {
                *(float2*)&PT[(m0 + g) * 72 + 8 * nt + 2 * tq]     = make_float2(acc[nt][0], acc[nt][1]);
                *(float2*)&PT[(m0 + g + 8) * 72 + 8 * nt + 2 * tq] = make_float2(acc[nt][2], acc[nt][3]);
            }
        }
        __syncthreads();

        // ---- P4b (mat0 only): add partials, pack OC pairs-along-c via shfl ----
        if (mat == 0) {
#pragma unroll
            for (int nt = 0; nt < 8; nt++) {
                float2 p0 = *(const float2*)&PT[(m0 + g) * 72 + 8 * nt + 2 * tq];
                float2 p1 = *(const float2*)&PT[(m0 + g + 8) * 72 + 8 * nt + 2 * tq];
                acc[nt][0] += p0.x; acc[nt][1] += p0.y;
                acc[nt][2] += p1.x; acc[nt][3] += p1.y;
            }
            const bool evn = ((g & 1) == 0);
#pragma unroll
            for (int nt = 0; nt < 8; nt++) {
                float pv0 = __shfl_xor_sync(FULL, acc[nt][0], 4);
                float pv1 = __shfl_xor_sync(FULL, acc[nt][1], 4);
                float pv2 = __shfl_xor_sync(FULL, acc[nt][2], 4);
                float pv3 = __shfl_xor_sync(FULL, acc[nt][3], 4);
                int c = 8 * nt + 2 * tq;
                uint2 w0, w1;
                int cw;
                if (evn) {
                    w0 = split_pair(acc[nt][0], pv0);
                    w1 = split_pair(acc[nt][1], pv1);
                    cw = (m0 + g) >> 1;
                } else {
                    w0 = split_pair(pv2, acc[nt][2]);
                    w1 = split_pair(pv3, acc[nt][3]);
                    cw = (m0 + g + 7) >> 1;
                }
                OCH[c * STR + cw] = w0.x;
                OCL[c * STR + cw] = w0.y;
                OCH[(c + 1) * STR + cw] = w1.x;
                OCL[(c + 1) * STR + cw] = w1.y;
            }
        }
    }
    __syncthreads();

    // ---- P6: proj y = PW @ O -> gmem (roll +4), float2 stores ----
    {
        const int n0 = (wid >> 2) * 32;
        float acc[4][4];
#pragma unroll
        for (int i = 0; i < 4; i++)
#pragma unroll
            for (int j = 0; j < 4; j++) acc[i][j] = 0.f;
        const unsigned och0 = sptr(OCH), ocl0 = sptr(OCL);
#pragma unroll
        for (int s = 0; s < 4; s++) {
            int recA = ((((wid & 3) * 4 + s) * 8 + g) * 4 + tq) * 2;
            uint4 A0 = __ldg(&g_pwf[recA]);
            uint4 A1v = __ldg(&g_pwf[recA + 1]);
            unsigned ah[4] = {A0.x, A0.z, A1v.x, A1v.z};
            unsigned al[4] = {A0.y, A0.w, A1v.y, A1v.w};
#pragma unroll
            for (int np = 0; np < 2; np++) {
                unsigned ro = (n0 + (np * 2 + ntl) * 8 + rr) * 144 + bB * 16 + s * 32;
                unsigned bhr[4], blr[4];
                ldsm4(bhr, och0 + ro);
                ldsm4(blr, ocl0 + ro);
                unsigned bh0[2] = {bhr[0], bhr[1]}, bl0[2] = {blr[0], blr[1]};
                unsigned bh1[2] = {bhr[2], bhr[3]}, bl1[2] = {blr[2], blr[3]};
                mma3(acc[np * 2],     ah, al, bh0, bl0);
                mma3(acc[np * 2 + 1], ah, al, bh1, bl1);
            }
        }
        float* ob = out + (size_t)b * 64 * HH * WW_;
#pragma unroll
        for (int nt = 0; nt < 4; nt++) {
            int c = n0 + 8 * nt + 2 * tq;
            int pi = c >> 3;
            int gh = (wh * 8 + pi + SHIFT) & 255;
            int gw = (ww * 8 + (c & 7) + SHIFT) & 255;
#pragma unroll
            for (int ri = 0; ri < 2; ri++) {
                int r = m0 + g + ri * 8;
                *(float2*)&ob[(size_t)r * HH * WW_ + (size_t)gh * WW_ + gw] =
                    make_float2(acc[nt][ri * 2], acc[nt][ri * 2 + 1]);
            }
        }
    }
}

extern "C" void kernel_launch(void* const* d_in, const int* in_sizes, int n_in,
                              void* d_out, int out_size) {
    const float* x      = (const float*)d_in[0];
    const float* q      = (const float*)d_in[1];
    const float* kv_w   = (const float*)d_in[2];
    const float* dw_w   = (const float*)d_in[3];
    const float* proj_w = (const float*)d_in[4];
    const float* rs1    = (const float*)d_in[5];
    const float* rs2    = (const float*)d_in[6];
    float* out = (float*)d_out;

    static bool attr_set = false;
    const int smem_bytes = 13824 * 4;  // 55,296 B
    if (!attr_set) {
        cudaFuncSetAttribute(win_kernel,
                             cudaFuncAttributeMaxDynamicSharedMemorySize,
                             smem_bytes);
        attr_set = true;
    }

    prep<<<32, 256>>>(q, kv_w, proj_w);
    win_kernel<<<8192, 256, smem_bytes>>>(x, dw_w, rs1, rs2, out);
}